// round 11
// baseline (speedup 1.0000x reference)
#include <cuda_runtime.h>
#include <cstdint>

// FeatureICA: 8192 independent (G=4, D=256) AuxICA solves, 10 iterations.
// Two positions per warp (16 lanes each). The 4x256 x-tile lives in shared
// memory (lane-interleaved u64 layout, conflict-free LDS.64). Key change this
// round: __launch_bounds__(128, 6) forces ptxas to <=84 regs so the smem tile
// actually buys occupancy (24 warps/SM instead of register-limited 16).
// Mask+Gram fused; mask u = 1/(|y|+eps) via MUFU rcp with the 1/D Gram factor
// folded in (floor dropped: would need |y| > 1e5, unreachable). 4x4 solve via
// row-k cofactors; normalization uses the scale-invariance of
// w/(sqrt(w'Vw)+eps) to absorb 1/det (sign restored via copysign). Output
// scale diag(inv(W)) premultiplied into W rows for the store.

#define NPOS   8192
#define GRP    4
#define DD     256
#define NPAIR  8          // u64 (f32x2) pairs per lane per group
#define NITER  10
#define WPB    4          // warps per block
#define HPB    (2 * WPB)  // positions (halves) per block

typedef unsigned long long u64;

__device__ __forceinline__ u64 pk2(float lo, float hi) {
    u64 r; asm("mov.b64 %0, {%1, %2};" : "=l"(r) : "f"(lo), "f"(hi)); return r;
}
__device__ __forceinline__ void upk2(u64 v, float& lo, float& hi) {
    asm("mov.b64 {%0, %1}, %2;" : "=f"(lo), "=f"(hi) : "l"(v));
}
__device__ __forceinline__ u64 fma2(u64 a, u64 b, u64 c) {
    u64 r; asm("fma.rn.f32x2 %0, %1, %2, %3;" : "=l"(r) : "l"(a), "l"(b), "l"(c)); return r;
}
__device__ __forceinline__ u64 mul2(u64 a, u64 b) {
    u64 r; asm("mul.rn.f32x2 %0, %1, %2;" : "=l"(r) : "l"(a), "l"(b)); return r;
}
__device__ __forceinline__ float frcp(float x) {
    float r; asm("rcp.approx.f32 %0, %1;" : "=f"(r) : "f"(x)); return r;
}
__device__ __forceinline__ float fsqrt_ap(float x) {
    float r; asm("sqrt.approx.f32 %0, %1;" : "=f"(r) : "f"(x)); return r;
}

__device__ __forceinline__ float det3(
    float a00, float a01, float a02,
    float a10, float a11, float a12,
    float a20, float a21, float a22) {
    return a00 * (a11 * a22 - a12 * a21)
         - a01 * (a10 * a22 - a12 * a20)
         + a02 * (a10 * a21 - a11 * a20);
}

__device__ __forceinline__ void idx3(int k, int& r0, int& r1, int& r2) {
    r0 = (k == 0) ? 1 : 0;
    r1 = (k <= 1) ? 2 : 1;
    r2 = (k <= 2) ? 3 : 2;
}

// Cofactor C_{k,i} of a 4x4 matrix (sign included); k,i compile-time consts.
__device__ __forceinline__ float cof(const float M[4][4], int k, int i) {
    int r0, r1, r2, c0, c1, c2;
    idx3(k, r0, r1, r2);
    idx3(i, c0, c1, c2);
    float d = det3(M[r0][c0], M[r0][c1], M[r0][c2],
                   M[r1][c0], M[r1][c1], M[r1][c2],
                   M[r2][c0], M[r2][c1], M[r2][c2]);
    return (((k + i) & 1) ? -d : d);
}

// Flat smem tile: [hid][g][j][l16] -> ((hid*GRP + g)*NPAIR + j)*16 + l16.
// Per half-warp row of 16 u64 = 128 B = all 32 banks; conflict-free.
__shared__ u64 s_tile[HPB * GRP * NPAIR * 16];

__device__ __forceinline__ u64 xt(const u64* tb, int g, int j) {
    return tb[(g * NPAIR + j) * 16];
}

__global__ void __launch_bounds__(WPB * 32, 6)
ica_kernel(const float* __restrict__ x, float* __restrict__ out) {
    const int lane = threadIdx.x & 31;
    const int half = lane >> 4;          // position index within the warp
    const int l16  = lane & 15;          // lane within the 16-lane half
    const int wib  = threadIdx.x >> 5;   // warp within block
    const int hid  = (wib << 1) + half;  // half-id within block
    const int pos  = (blockIdx.x * WPB + wib) * 2 + half;

    const float* xp = x + (size_t)pos * (GRP * DD);
    u64* tbase = &s_tile[hid * (GRP * NPAIR * 16) + l16];

    // Stage tile straight into smem (no register staging array -- keeps the
    // prologue's register pressure low; L1tex queue supplies the MLP).
    // Lane l16 owns pairs {d = 32j + 2*l16, +1}; each (g,j) half-warp
    // transaction covers 16 consecutive u64 = 128 B.
    #pragma unroll
    for (int g = 0; g < GRP; g++)
        #pragma unroll
        for (int j = 0; j < NPAIR; j++)
            tbase[(g * NPAIR + j) * 16] =
                ((const u64*)(xp + g * DD + j * 32))[l16];
    __syncwarp();

    float W[4][4] = {{1.f,0.f,0.f,0.f},{0.f,1.f,0.f,0.f},
                     {0.f,0.f,1.f,0.f},{0.f,0.f,0.f,1.f}};

    const float eps    = 1e-5f;
    const float RSCALE = 256.0f;           // fold 1/D into the mask
    const float RBIAS  = 256.0f * 1e-5f;   // 256 * eps

    #pragma unroll 1
    for (int it = 0; it < NITER; it++) {
        #pragma unroll
        for (int k = 0; k < GRP; k++) {
            u64 wb0 = pk2(W[k][0], W[k][0]);
            u64 wb1 = pk2(W[k][1], W[k][1]);
            u64 wb2 = pk2(W[k][2], W[k][2]);
            u64 wb3 = pk2(W[k][3], W[k][3]);

            // Fused mask + weighted Gram (10 unique symmetric entries).
            u64 p00=0,p01=0,p02=0,p03=0,p11=0,p12=0,p13=0,p22=0,p23=0,p33=0;
            #pragma unroll
            for (int j = 0; j < NPAIR; j++) {
                u64 x0 = xt(tbase, 0, j);
                u64 x1 = xt(tbase, 1, j);
                u64 x2 = xt(tbase, 2, j);
                u64 x3 = xt(tbase, 3, j);
                u64 y2 = mul2(wb0, x0);
                y2 = fma2(wb1, x1, y2);
                y2 = fma2(wb2, x2, y2);
                y2 = fma2(wb3, x3, y2);
                float y0, y1;
                upk2(y2, y0, y1);
                float r0 = fmaf(fabsf(y0), RSCALE, RBIAS);
                float r1 = fmaf(fabsf(y1), RSCALE, RBIAS);
                u64 uu = pk2(frcp(r0), frcp(r1));

                u64 t0 = mul2(uu, x0);
                u64 t1 = mul2(uu, x1);
                u64 t2 = mul2(uu, x2);
                u64 t3 = mul2(uu, x3);
                p00 = fma2(t0, x0, p00);
                p01 = fma2(t0, x1, p01);
                p02 = fma2(t0, x2, p02);
                p03 = fma2(t0, x3, p03);
                p11 = fma2(t1, x1, p11);
                p12 = fma2(t1, x2, p12);
                p13 = fma2(t1, x3, p13);
                p22 = fma2(t2, x2, p22);
                p23 = fma2(t2, x3, p23);
                p33 = fma2(t3, x3, p33);
            }

            // Packed -> scalar horizontal add.
            float ha, hb;
            float s00, s01, s02, s03, s11, s12, s13, s22, s23, s33;
            upk2(p00, ha, hb); s00 = ha + hb;
            upk2(p01, ha, hb); s01 = ha + hb;
            upk2(p02, ha, hb); s02 = ha + hb;
            upk2(p03, ha, hb); s03 = ha + hb;
            upk2(p11, ha, hb); s11 = ha + hb;
            upk2(p12, ha, hb); s12 = ha + hb;
            upk2(p13, ha, hb); s13 = ha + hb;
            upk2(p22, ha, hb); s22 = ha + hb;
            upk2(p23, ha, hb); s23 = ha + hb;
            upk2(p33, ha, hb); s33 = ha + hb;

            // 4-level butterfly; offsets 8,4,2,1 stay within each 16-lane half.
            #pragma unroll
            for (int off = 8; off > 0; off >>= 1) {
                s00 += __shfl_xor_sync(0xffffffffu, s00, off);
                s01 += __shfl_xor_sync(0xffffffffu, s01, off);
                s02 += __shfl_xor_sync(0xffffffffu, s02, off);
                s03 += __shfl_xor_sync(0xffffffffu, s03, off);
                s11 += __shfl_xor_sync(0xffffffffu, s11, off);
                s12 += __shfl_xor_sync(0xffffffffu, s12, off);
                s13 += __shfl_xor_sync(0xffffffffu, s13, off);
                s22 += __shfl_xor_sync(0xffffffffu, s22, off);
                s23 += __shfl_xor_sync(0xffffffffu, s23, off);
                s33 += __shfl_xor_sync(0xffffffffu, s33, off);
            }

            // V (symmetric; already includes the 1/D factor via the mask).
            float V[4][4];
            V[0][0] = s00;
            V[0][1] = V[1][0] = s01;
            V[0][2] = V[2][0] = s02;
            V[0][3] = V[3][0] = s03;
            V[1][1] = s11;
            V[1][2] = V[2][1] = s12;
            V[1][3] = V[3][1] = s13;
            V[2][2] = s22;
            V[2][3] = V[3][2] = s23;
            V[3][3] = s33;

            // M = W @ V with the current (partially updated) W.
            float M[4][4];
            #pragma unroll
            for (int r = 0; r < 4; r++)
                #pragma unroll
                for (int c = 0; c < 4; c++) {
                    float s = W[r][0] * V[0][c];
                    s = fmaf(W[r][1], V[1][c], s);
                    s = fmaf(W[r][2], V[2][c], s);
                    s = fmaf(W[r][3], V[3][c], s);
                    M[r][c] = s;
                }

            // Row-k cofactors: solution of M w = e_k is c/det.
            float c0 = cof(M, k, 0);
            float c1 = cof(M, k, 1);
            float c2 = cof(M, k, 2);
            float c3 = cof(M, k, 3);
            float det = M[k][0]*c0 + M[k][1]*c1 + M[k][2]*c2 + M[k][3]*c3;

            // w/(sqrt(w'Vw)+eps) is scale-invariant up to sign:
            // W[k] = c * copysign(1/(sqrt(c'Vc) + eps*|det|), det).
            float t0 = V[0][0]*c0 + V[0][1]*c1 + V[0][2]*c2 + V[0][3]*c3;
            float t1 = V[1][0]*c0 + V[1][1]*c1 + V[1][2]*c2 + V[1][3]*c3;
            float t2 = V[2][0]*c0 + V[2][1]*c1 + V[2][2]*c2 + V[2][3]*c3;
            float t3 = V[3][0]*c0 + V[3][1]*c1 + V[3][2]*c2 + V[3][3]*c3;
            float s  = c0*t0 + c1*t1 + c2*t2 + c3*t3;
            float denom = fmaf(eps, fabsf(det), fsqrt_ap(s));
            float inv = copysignf(frcp(denom), det);
            W[k][0] = c0 * inv;
            W[k][1] = c1 * inv;
            W[k][2] = c2 * inv;
            W[k][3] = c3 * inv;
        }
    }

    // scale_g = diag(inv(W))_g = C_{g,g}(W) / det(W); premultiply into rows.
    float d0 = cof(W, 0, 0);
    float d1 = cof(W, 0, 1);
    float d2 = cof(W, 0, 2);
    float d3 = cof(W, 0, 3);
    float detW = W[0][0]*d0 + W[0][1]*d1 + W[0][2]*d2 + W[0][3]*d3;
    float idetW = frcp(detW);
    float scale[4];
    scale[0] = d0 * idetW;
    scale[1] = cof(W, 1, 1) * idetW;
    scale[2] = cof(W, 2, 2) * idetW;
    scale[3] = cof(W, 3, 3) * idetW;

    float* op = out + (size_t)pos * (GRP * DD);
    #pragma unroll
    for (int g = 0; g < GRP; g++) {
        // Fold the output scale into the broadcast row (saves a mul2 per j).
        float a0 = W[g][0] * scale[g];
        float a1 = W[g][1] * scale[g];
        float a2 = W[g][2] * scale[g];
        float a3 = W[g][3] * scale[g];
        u64 wb0 = pk2(a0, a0);
        u64 wb1 = pk2(a1, a1);
        u64 wb2 = pk2(a2, a2);
        u64 wb3 = pk2(a3, a3);
        #pragma unroll
        for (int j = 0; j < NPAIR; j++) {
            u64 y2 = mul2(wb0, xt(tbase, 0, j));
            y2 = fma2(wb1, xt(tbase, 1, j), y2);
            y2 = fma2(wb2, xt(tbase, 2, j), y2);
            y2 = fma2(wb3, xt(tbase, 3, j), y2);
            ((u64*)(op + g * DD + j * 32))[l16] = y2;
        }
    }
}

extern "C" void kernel_launch(void* const* d_in, const int* in_sizes, int n_in,
                              void* d_out, int out_size) {
    const float* x = (const float*)d_in[0];
    float* out = (float*)d_out;
    (void)in_sizes; (void)n_in; (void)out_size;
    // 8192 positions, 2 per warp, WPB warps per block.
    ica_kernel<<<NPOS / HPB, WPB * 32>>>(x, out);
}

// round 12
// speedup vs baseline: 1.5378x; 1.5378x over previous
#include <cuda_runtime.h>
#include <cstdint>

// FeatureICA: 8192 independent (G=4, D=256) AuxICA solves, 10 iterations.
// FOUR positions per warp (8 lanes each, 64-thread blocks). The per-k-step
// warp-uniform 4x4 algebra (~200 instrs) and the (now 3-level) butterfly are
// amortized over 4 positions. x-tile in shared memory, layout
// tile[g][j][pos_in_block][l8] so each warp LDS.64 covers 32 consecutive u64
// = all 32 banks (conflict-free). 1024 blocks x 64 thr, 32KB smem, ~128 regs
// -> 7 blocks/SM, single wave (148*7=1036 >= 1024), no wave tail.
// Mask u = 1/(|y|+eps) via MUFU rcp with 1/D folded in (floor dropped:
// would need |y| > 1e5, unreachable). 4x4 solve via row-k cofactors;
// normalization uses scale-invariance of w/(sqrt(w'Vw)+eps) to absorb 1/det.
// Output scale diag(inv(W)) premultiplied into W rows. NO launch-bounds reg
// cap (round-11 lesson: caps -> local-memory spills -> 1.5x regression).

#define NPOS   8192
#define GRP    4
#define DD     256
#define NPAIR  16         // u64 (f32x2) pairs per lane per group (32 floats)
#define NITER  10
#define WPB    2          // warps per block (64 threads)
#define POSB   8          // positions per block (4 per warp)

typedef unsigned long long u64;

__device__ __forceinline__ u64 pk2(float lo, float hi) {
    u64 r; asm("mov.b64 %0, {%1, %2};" : "=l"(r) : "f"(lo), "f"(hi)); return r;
}
__device__ __forceinline__ void upk2(u64 v, float& lo, float& hi) {
    asm("mov.b64 {%0, %1}, %2;" : "=f"(lo), "=f"(hi) : "l"(v));
}
__device__ __forceinline__ u64 fma2(u64 a, u64 b, u64 c) {
    u64 r; asm("fma.rn.f32x2 %0, %1, %2, %3;" : "=l"(r) : "l"(a), "l"(b), "l"(c)); return r;
}
__device__ __forceinline__ u64 mul2(u64 a, u64 b) {
    u64 r; asm("mul.rn.f32x2 %0, %1, %2;" : "=l"(r) : "l"(a), "l"(b)); return r;
}
__device__ __forceinline__ float frcp(float x) {
    float r; asm("rcp.approx.f32 %0, %1;" : "=f"(r) : "f"(x)); return r;
}
__device__ __forceinline__ float fsqrt_ap(float x) {
    float r; asm("sqrt.approx.f32 %0, %1;" : "=f"(r) : "f"(x)); return r;
}

__device__ __forceinline__ float det3(
    float a00, float a01, float a02,
    float a10, float a11, float a12,
    float a20, float a21, float a22) {
    return a00 * (a11 * a22 - a12 * a21)
         - a01 * (a10 * a22 - a12 * a20)
         + a02 * (a10 * a21 - a11 * a20);
}

__device__ __forceinline__ void idx3(int k, int& r0, int& r1, int& r2) {
    r0 = (k == 0) ? 1 : 0;
    r1 = (k <= 1) ? 2 : 1;
    r2 = (k <= 2) ? 3 : 2;
}

// Cofactor C_{k,i} of a 4x4 matrix (sign included); k,i compile-time consts.
__device__ __forceinline__ float cof(const float M[4][4], int k, int i) {
    int r0, r1, r2, c0, c1, c2;
    idx3(k, r0, r1, r2);
    idx3(i, c0, c1, c2);
    float d = det3(M[r0][c0], M[r0][c1], M[r0][c2],
                   M[r1][c0], M[r1][c1], M[r1][c2],
                   M[r2][c0], M[r2][c1], M[r2][c2]);
    return (((k + i) & 1) ? -d : d);
}

// Smem tile: [g][j][pos_in_block][l8] -> ((g*NPAIR + j)*POSB + p)*8 + l8.
// Fixed (g,j): a warp's 32 lanes (4 positions x 8 lanes) address 32
// consecutive u64 = 256B = all 32 banks, conflict-free.
__shared__ u64 s_tile[GRP * NPAIR * POSB * 8];

__device__ __forceinline__ u64 xt(const u64* tb, int g, int j) {
    return tb[(g * NPAIR + j) * (POSB * 8)];
}

__global__ void __launch_bounds__(WPB * 32)
ica_kernel(const float* __restrict__ x, float* __restrict__ out) {
    const int lane = threadIdx.x & 31;
    const int l8   = lane & 7;           // lane within the 8-lane quarter
    const int wib  = threadIdx.x >> 5;   // warp within block
    const int p    = (wib << 2) + (lane >> 3);  // position within block
    const int pos  = blockIdx.x * POSB + p;

    const float* xp = x + (size_t)pos * (GRP * DD);
    u64* tbase = &s_tile[p * 8 + l8];

    // Stage tile into smem. Lane l8 owns pairs {d = 16j + 2*l8, +1}.
    // Global side: each quarter reads 8 consecutive u64 = 64B; the warp's
    // 4 quarters touch exactly 8 sectors (256B) per instruction.
    #pragma unroll
    for (int g = 0; g < GRP; g++)
        #pragma unroll
        for (int j = 0; j < NPAIR; j++)
            tbase[(g * NPAIR + j) * (POSB * 8)] =
                ((const u64*)(xp + g * DD + j * 16))[l8];
    __syncwarp();

    float W[4][4] = {{1.f,0.f,0.f,0.f},{0.f,1.f,0.f,0.f},
                     {0.f,0.f,1.f,0.f},{0.f,0.f,0.f,1.f}};

    const float eps    = 1e-5f;
    const float RSCALE = 256.0f;           // fold 1/D into the mask
    const float RBIAS  = 256.0f * 1e-5f;   // 256 * eps

    #pragma unroll 1
    for (int it = 0; it < NITER; it++) {
        #pragma unroll
        for (int k = 0; k < GRP; k++) {
            u64 wb0 = pk2(W[k][0], W[k][0]);
            u64 wb1 = pk2(W[k][1], W[k][1]);
            u64 wb2 = pk2(W[k][2], W[k][2]);
            u64 wb3 = pk2(W[k][3], W[k][3]);

            // Fused mask + weighted Gram (10 unique symmetric entries).
            u64 p00=0,p01=0,p02=0,p03=0,p11=0,p12=0,p13=0,p22=0,p23=0,p33=0;
            #pragma unroll
            for (int j = 0; j < NPAIR; j++) {
                u64 x0 = xt(tbase, 0, j);
                u64 x1 = xt(tbase, 1, j);
                u64 x2 = xt(tbase, 2, j);
                u64 x3 = xt(tbase, 3, j);
                u64 y2 = mul2(wb0, x0);
                y2 = fma2(wb1, x1, y2);
                y2 = fma2(wb2, x2, y2);
                y2 = fma2(wb3, x3, y2);
                float y0, y1;
                upk2(y2, y0, y1);
                float r0 = fmaf(fabsf(y0), RSCALE, RBIAS);
                float r1 = fmaf(fabsf(y1), RSCALE, RBIAS);
                u64 uu = pk2(frcp(r0), frcp(r1));

                u64 t0 = mul2(uu, x0);
                u64 t1 = mul2(uu, x1);
                u64 t2 = mul2(uu, x2);
                u64 t3 = mul2(uu, x3);
                p00 = fma2(t0, x0, p00);
                p01 = fma2(t0, x1, p01);
                p02 = fma2(t0, x2, p02);
                p03 = fma2(t0, x3, p03);
                p11 = fma2(t1, x1, p11);
                p12 = fma2(t1, x2, p12);
                p13 = fma2(t1, x3, p13);
                p22 = fma2(t2, x2, p22);
                p23 = fma2(t2, x3, p23);
                p33 = fma2(t3, x3, p33);
            }

            // Packed -> scalar horizontal add.
            float ha, hb;
            float s00, s01, s02, s03, s11, s12, s13, s22, s23, s33;
            upk2(p00, ha, hb); s00 = ha + hb;
            upk2(p01, ha, hb); s01 = ha + hb;
            upk2(p02, ha, hb); s02 = ha + hb;
            upk2(p03, ha, hb); s03 = ha + hb;
            upk2(p11, ha, hb); s11 = ha + hb;
            upk2(p12, ha, hb); s12 = ha + hb;
            upk2(p13, ha, hb); s13 = ha + hb;
            upk2(p22, ha, hb); s22 = ha + hb;
            upk2(p23, ha, hb); s23 = ha + hb;
            upk2(p33, ha, hb); s33 = ha + hb;

            // 3-level butterfly; offsets 4,2,1 stay within each 8-lane quarter.
            #pragma unroll
            for (int off = 4; off > 0; off >>= 1) {
                s00 += __shfl_xor_sync(0xffffffffu, s00, off);
                s01 += __shfl_xor_sync(0xffffffffu, s01, off);
                s02 += __shfl_xor_sync(0xffffffffu, s02, off);
                s03 += __shfl_xor_sync(0xffffffffu, s03, off);
                s11 += __shfl_xor_sync(0xffffffffu, s11, off);
                s12 += __shfl_xor_sync(0xffffffffu, s12, off);
                s13 += __shfl_xor_sync(0xffffffffu, s13, off);
                s22 += __shfl_xor_sync(0xffffffffu, s22, off);
                s23 += __shfl_xor_sync(0xffffffffu, s23, off);
                s33 += __shfl_xor_sync(0xffffffffu, s33, off);
            }

            // V (symmetric; already includes the 1/D factor via the mask).
            float V[4][4];
            V[0][0] = s00;
            V[0][1] = V[1][0] = s01;
            V[0][2] = V[2][0] = s02;
            V[0][3] = V[3][0] = s03;
            V[1][1] = s11;
            V[1][2] = V[2][1] = s12;
            V[1][3] = V[3][1] = s13;
            V[2][2] = s22;
            V[2][3] = V[3][2] = s23;
            V[3][3] = s33;

            // M = W @ V with the current (partially updated) W.
            float M[4][4];
            #pragma unroll
            for (int r = 0; r < 4; r++)
                #pragma unroll
                for (int c = 0; c < 4; c++) {
                    float s = W[r][0] * V[0][c];
                    s = fmaf(W[r][1], V[1][c], s);
                    s = fmaf(W[r][2], V[2][c], s);
                    s = fmaf(W[r][3], V[3][c], s);
                    M[r][c] = s;
                }

            // Row-k cofactors: solution of M w = e_k is c/det.
            float c0 = cof(M, k, 0);
            float c1 = cof(M, k, 1);
            float c2 = cof(M, k, 2);
            float c3 = cof(M, k, 3);
            float det = M[k][0]*c0 + M[k][1]*c1 + M[k][2]*c2 + M[k][3]*c3;

            // w/(sqrt(w'Vw)+eps) is scale-invariant up to sign:
            // W[k] = c * copysign(1/(sqrt(c'Vc) + eps*|det|), det).
            float t0 = V[0][0]*c0 + V[0][1]*c1 + V[0][2]*c2 + V[0][3]*c3;
            float t1 = V[1][0]*c0 + V[1][1]*c1 + V[1][2]*c2 + V[1][3]*c3;
            float t2 = V[2][0]*c0 + V[2][1]*c1 + V[2][2]*c2 + V[2][3]*c3;
            float t3 = V[3][0]*c0 + V[3][1]*c1 + V[3][2]*c2 + V[3][3]*c3;
            float s  = c0*t0 + c1*t1 + c2*t2 + c3*t3;
            float denom = fmaf(eps, fabsf(det), fsqrt_ap(s));
            float inv = copysignf(frcp(denom), det);
            W[k][0] = c0 * inv;
            W[k][1] = c1 * inv;
            W[k][2] = c2 * inv;
            W[k][3] = c3 * inv;
        }
    }

    // scale_g = diag(inv(W))_g = C_{g,g}(W) / det(W); premultiply into rows.
    float d0 = cof(W, 0, 0);
    float d1 = cof(W, 0, 1);
    float d2 = cof(W, 0, 2);
    float d3 = cof(W, 0, 3);
    float detW = W[0][0]*d0 + W[0][1]*d1 + W[0][2]*d2 + W[0][3]*d3;
    float idetW = frcp(detW);
    float scale[4];
    scale[0] = d0 * idetW;
    scale[1] = cof(W, 1, 1) * idetW;
    scale[2] = cof(W, 2, 2) * idetW;
    scale[3] = cof(W, 3, 3) * idetW;

    float* op = out + (size_t)pos * (GRP * DD);
    #pragma unroll
    for (int g = 0; g < GRP; g++) {
        // Fold the output scale into the broadcast row.
        float a0 = W[g][0] * scale[g];
        float a1 = W[g][1] * scale[g];
        float a2 = W[g][2] * scale[g];
        float a3 = W[g][3] * scale[g];
        u64 wb0 = pk2(a0, a0);
        u64 wb1 = pk2(a1, a1);
        u64 wb2 = pk2(a2, a2);
        u64 wb3 = pk2(a3, a3);
        #pragma unroll
        for (int j = 0; j < NPAIR; j++) {
            u64 y2 = mul2(wb0, xt(tbase, 0, j));
            y2 = fma2(wb1, xt(tbase, 1, j), y2);
            y2 = fma2(wb2, xt(tbase, 2, j), y2);
            y2 = fma2(wb3, xt(tbase, 3, j), y2);
            ((u64*)(op + g * DD + j * 16))[l8] = y2;
        }
    }
}

extern "C" void kernel_launch(void* const* d_in, const int* in_sizes, int n_in,
                              void* d_out, int out_size) {
    const float* x = (const float*)d_in[0];
    float* out = (float*)d_out;
    (void)in_sizes; (void)n_in; (void)out_size;
    // 8192 positions, 8 per block (4 per warp, 2 warps) -> 1024 blocks.
    ica_kernel<<<NPOS / POSB, WPB * 32>>>(x, out);
}